// round 3
// baseline (speedup 1.0000x reference)
#include <cuda_runtime.h>
#include <cstdint>

// ---------------------------------------------------------------------------
// AxialAttention: x [8,128,128,128] fp32, 8 heads, head dim 16.
// Pass 0: attend along H (sequences indexed by (b, w))
// Pass 1: attend along W (sequences indexed by (b, h)), adds into pass-0 output.
// One CTA per sequence. Fully fused: QKV proj + softmax attention + out proj.
// ---------------------------------------------------------------------------

#define NTHREADS 256
#define NHEADS   8
#define HDIM     16
#define XSTRIDE  132   // 128 + 4 pad (float4-aligned, avoids 32-way conflicts)

static constexpr int XS_OFF = 0;
static constexpr int KS_OFF = 128 * XSTRIDE;
static constexpr int VS_OFF = 2 * 128 * XSTRIDE;
static constexpr int WC_OFF = 3 * 128 * XSTRIDE;          // 4096-float weight staging
static constexpr int SMEM_FLOATS = 3 * 128 * XSTRIDE + 4096;
static constexpr int SMEM_BYTES  = SMEM_FLOATS * 4;       // 219,136 B

template <int PASS>
__global__ __launch_bounds__(NTHREADS, 1)
void axial_attn_kernel(const float* __restrict__ x,
                       const float* __restrict__ Wq,
                       const float* __restrict__ Wkv,
                       const float* __restrict__ Wo,
                       const float* __restrict__ bo,
                       float* __restrict__ out)
{
    extern __shared__ float sm[];
    float* Xs = sm + XS_OFF;
    float* Ks = sm + KS_OFF;
    float* Vs = sm + VS_OFF;
    float* Wc = sm + WC_OFF;

    const int t  = threadIdx.x;
    const int r  = t >> 1;      // query row (token) 0..127
    const int hf = t & 1;       // half: j-range / k-range / col-range split

    const int seq = blockIdx.x; // 0..1023
    const int b   = seq >> 7;
    const int s   = seq & 127;

    // token i lives at x[base + i*istride + d]
    const int base    = b * (128 * 128 * 128) + (PASS == 0 ? s * 128 : s * 16384);
    const int istride = (PASS == 0 ? 16384 : 128);

    // ---------------- Phase 1: load X tile ----------------
    {
        const float* src = x + base + r * istride + hf * 64;
        float* dst = Xs + r * XSTRIDE + hf * 64;
        #pragma unroll
        for (int i = 0; i < 16; i++) {
            float4 v = reinterpret_cast<const float4*>(src)[i];
            reinterpret_cast<float4*>(dst)[i] = v;
        }
    }

    // ---------------- Phase 2: K and V projections ----------------
    // K = X @ Wkv[:, 0:128], V = X @ Wkv[:, 128:256]; chunked by 32 output cols.
    for (int kv = 0; kv < 2; kv++) {
        const int colofs = kv * 128;
        float* dstS = (kv == 0) ? Ks : Vs;
        for (int chunk = 0; chunk < 4; chunk++) {
            __syncthreads();  // also covers phase-1 completion on first iter
            // stage Wc[k][c], k=0..127, c=0..31
            #pragma unroll
            for (int i = 0; i < 16; i++) {
                int f = t + i * NTHREADS;          // 0..4095
                int k = f >> 5, c = f & 31;
                Wc[f] = Wkv[k * 256 + colofs + chunk * 32 + c];
            }
            __syncthreads();
            float acc[16];
            #pragma unroll
            for (int e = 0; e < 16; e++) acc[e] = 0.f;
            const float* xr = Xs + r * XSTRIDE;
            const int wofs = hf * 16;
            #pragma unroll 8
            for (int k = 0; k < 128; k++) {
                float xv = xr[k];
                const float4* wr = reinterpret_cast<const float4*>(Wc + k * 32 + wofs);
                #pragma unroll
                for (int e4 = 0; e4 < 4; e4++) {
                    float4 w = wr[e4];
                    acc[e4 * 4 + 0] += xv * w.x;
                    acc[e4 * 4 + 1] += xv * w.y;
                    acc[e4 * 4 + 2] += xv * w.z;
                    acc[e4 * 4 + 3] += xv * w.w;
                }
            }
            float* drow = dstS + r * XSTRIDE + chunk * 32 + hf * 16;
            #pragma unroll
            for (int e4 = 0; e4 < 4; e4++)
                reinterpret_cast<float4*>(drow)[e4] =
                    make_float4(acc[e4 * 4 + 0], acc[e4 * 4 + 1],
                                acc[e4 * 4 + 2], acc[e4 * 4 + 3]);
        }
    }

    // ---------------- Phase 3: attention + incremental out-proj ----------------
    float y[64];
    #pragma unroll
    for (int c = 0; c < 64; c++) y[c] = 0.f;

    const int jbase = hf * 64;   // this thread's key half
    const int cbase = hf * 64;   // this thread's output-column half

    for (int h = 0; h < NHEADS; h++) {
        __syncthreads();  // previous users of Wc (and K/V writes on first iter) done
        // stage WqC (128x16) in Wc[0..2047], WoC (16x128) in Wc[2048..4095]
        #pragma unroll
        for (int i = 0; i < 8; i++) {
            int f = t + i * NTHREADS;              // 0..2047
            int k = f >> 4, e = f & 15;
            Wc[f] = Wq[k * 128 + h * 16 + e];
        }
        #pragma unroll
        for (int i = 0; i < 8; i++) {
            int f = t + i * NTHREADS;
            int e = f >> 7, c = f & 127;
            Wc[2048 + f] = Wo[(h * 16 + e) * 128 + c];
        }
        __syncthreads();

        // q_h (k-range split across pair, then combined); scale folded in
        float qe[16];
        #pragma unroll
        for (int e = 0; e < 16; e++) qe[e] = 0.f;
        {
            const float* xr = Xs + r * XSTRIDE + hf * 64;
            #pragma unroll 8
            for (int kk = 0; kk < 64; kk++) {
                float xv = xr[kk];
                const float4* wr = reinterpret_cast<const float4*>(Wc + (hf * 64 + kk) * 16);
                #pragma unroll
                for (int e4 = 0; e4 < 4; e4++) {
                    float4 w = wr[e4];
                    qe[e4 * 4 + 0] += xv * w.x;
                    qe[e4 * 4 + 1] += xv * w.y;
                    qe[e4 * 4 + 2] += xv * w.z;
                    qe[e4 * 4 + 3] += xv * w.w;
                }
            }
        }
        #pragma unroll
        for (int e = 0; e < 16; e++) {
            qe[e] += __shfl_xor_sync(0xffffffffu, qe[e], 1);
            qe[e] *= 0.25f;   // 1/sqrt(16)
        }

        // dots (this thread's 64 keys), track max; blocked 16 at a time
        float d[64];
        float m = -1e30f;
        #pragma unroll
        for (int blk = 0; blk < 4; blk++) {
            #pragma unroll
            for (int j2 = 0; j2 < 16; j2++) {
                const int jj = blk * 16 + j2;
                const float4* kr = reinterpret_cast<const float4*>(
                    Ks + (jbase + jj) * XSTRIDE + h * HDIM);
                float sdot = 0.f;
                #pragma unroll
                for (int e4 = 0; e4 < 4; e4++) {
                    float4 k4 = kr[e4];
                    sdot += qe[e4 * 4 + 0] * k4.x + qe[e4 * 4 + 1] * k4.y
                          + qe[e4 * 4 + 2] * k4.z + qe[e4 * 4 + 3] * k4.w;
                }
                d[jj] = sdot;
                m = fmaxf(m, sdot);
            }
        }
        m = fmaxf(m, __shfl_xor_sync(0xffffffffu, m, 1));

        // exp + sum + AV, blocked 16 at a time to keep live set small
        float oe[16];
        #pragma unroll
        for (int e = 0; e < 16; e++) oe[e] = 0.f;
        float l = 0.f;
        #pragma unroll
        for (int blk = 0; blk < 4; blk++) {
            #pragma unroll
            for (int j2 = 0; j2 < 16; j2++) {
                const int jj = blk * 16 + j2;
                float p = __expf(d[jj] - m);
                l += p;
                const float4* vr = reinterpret_cast<const float4*>(
                    Vs + (jbase + jj) * XSTRIDE + h * HDIM);
                #pragma unroll
                for (int e4 = 0; e4 < 4; e4++) {
                    float4 v4 = vr[e4];
                    oe[e4 * 4 + 0] += p * v4.x;
                    oe[e4 * 4 + 1] += p * v4.y;
                    oe[e4 * 4 + 2] += p * v4.z;
                    oe[e4 * 4 + 3] += p * v4.w;
                }
            }
        }
        l += __shfl_xor_sync(0xffffffffu, l, 1);
        float inv = 1.0f / l;
        #pragma unroll
        for (int e = 0; e < 16; e++) {
            oe[e] += __shfl_xor_sync(0xffffffffu, oe[e], 1);
            oe[e] *= inv;
        }

        // y[c] += sum_e oe[e] * Wo[h*16+e][cbase + c]
        #pragma unroll
        for (int e = 0; e < 16; e++) {
            const float4* wr = reinterpret_cast<const float4*>(Wc + 2048 + e * 128 + cbase);
            float ov = oe[e];
            #pragma unroll
            for (int c4 = 0; c4 < 16; c4++) {
                float4 w = wr[c4];
                y[c4 * 4 + 0] += ov * w.x;
                y[c4 * 4 + 1] += ov * w.y;
                y[c4 * 4 + 2] += ov * w.z;
                y[c4 * 4 + 3] += ov * w.w;
            }
        }
    }

    // ---------------- Phase 4: bias + write (pass1 accumulates) ----------------
    {
        const float4* bp = reinterpret_cast<const float4*>(bo + cbase);
        float* op = out + base + r * istride + cbase;
        #pragma unroll
        for (int c4 = 0; c4 < 16; c4++) {
            float4 bv = bp[c4];
            float4 w;
            w.x = y[c4 * 4 + 0] + bv.x;
            w.y = y[c4 * 4 + 1] + bv.y;
            w.z = y[c4 * 4 + 2] + bv.z;
            w.w = y[c4 * 4 + 3] + bv.w;
            if (PASS == 1) {
                float4 prev = reinterpret_cast<const float4*>(op)[c4];
                w.x += prev.x; w.y += prev.y; w.z += prev.z; w.w += prev.w;
            }
            reinterpret_cast<float4*>(op)[c4] = w;
        }
    }
}

extern "C" void kernel_launch(void* const* d_in, const int* in_sizes, int n_in,
                              void* d_out, int out_size)
{
    const float* x    = (const float*)d_in[0];
    const float* Wq0  = (const float*)d_in[1];
    const float* Wkv0 = (const float*)d_in[2];
    const float* Wo0  = (const float*)d_in[3];
    const float* bo0  = (const float*)d_in[4];
    const float* Wq1  = (const float*)d_in[5];
    const float* Wkv1 = (const float*)d_in[6];
    const float* Wo1  = (const float*)d_in[7];
    const float* bo1  = (const float*)d_in[8];
    float* out = (float*)d_out;

    cudaFuncSetAttribute(axial_attn_kernel<0>,
                         cudaFuncAttributeMaxDynamicSharedMemorySize, SMEM_BYTES);
    cudaFuncSetAttribute(axial_attn_kernel<1>,
                         cudaFuncAttributeMaxDynamicSharedMemorySize, SMEM_BYTES);

    // pass 0 writes out, pass 1 (stream-ordered after) reads+adds+writes
    axial_attn_kernel<0><<<1024, NTHREADS, SMEM_BYTES>>>(x, Wq0, Wkv0, Wo0, bo0, out);
    axial_attn_kernel<1><<<1024, NTHREADS, SMEM_BYTES>>>(x, Wq1, Wkv1, Wo1, bo1, out);
}

// round 5
// speedup vs baseline: 1.5048x; 1.5048x over previous
#include <cuda_runtime.h>
#include <cstdint>

// ---------------------------------------------------------------------------
// AxialAttention: x [8,128,128,128] fp32, 8 heads, head dim 16.
// Pass 0: attend along H; Pass 1: attend along W, accumulating into output.
// One CTA per sequence (128 tokens x 128 dim). Fully fused.
// R4 = R3 redesign (never benched due to infra failure), resubmitted:
//  - Q precomputed once (GEMM), stored over the dead X tile.
//  - 4x4 register-blocked projections: 8 FMA per LDS.128.
//  - Attention: 2 query rows x 32 interleaved keys per thread: 8 FMA/LDS.128,
//    conflict-free (key = 4*jj+qf puts the 4 per-warp addrs in disjoint banks).
// ---------------------------------------------------------------------------

#define NTHREADS 256
#define NHEADS   8
#define XSTRIDE  132   // 128 + 4 pad, float4-aligned

static constexpr int KS_OFF = 128 * XSTRIDE;
static constexpr int VS_OFF = 2 * 128 * XSTRIDE;
static constexpr int WC_OFF = 3 * 128 * XSTRIDE;          // 4096-float staging
static constexpr int SMEM_FLOATS = 3 * 128 * XSTRIDE + 4096;
static constexpr int SMEM_BYTES  = SMEM_FLOATS * 4;       // 219,136 B

// One 32-col chunk of a [128,128] GEMM: rows {rg,rg+32,rg+64,rg+96},
// cols {4cq..4cq+3} within the chunk. Wc holds W[k][0..31] for this chunk.
__device__ __forceinline__ void gemm_chunk_4x4(const float* __restrict__ Xs,
                                               const float* __restrict__ Wc,
                                               int rg, int cq, float4 acc[4])
{
    #pragma unroll
    for (int i = 0; i < 4; i++) acc[i] = make_float4(0.f, 0.f, 0.f, 0.f);
    #pragma unroll 8
    for (int kb = 0; kb < 32; kb++) {
        float4 xv[4];
        #pragma unroll
        for (int i = 0; i < 4; i++)
            xv[i] = *reinterpret_cast<const float4*>(Xs + (rg + 32 * i) * XSTRIDE + kb * 4);
        float4 wv[4];
        #pragma unroll
        for (int k2 = 0; k2 < 4; k2++)
            wv[k2] = *reinterpret_cast<const float4*>(Wc + (kb * 4 + k2) * 32 + cq * 4);
        #pragma unroll
        for (int i = 0; i < 4; i++) {
            acc[i].x += xv[i].x * wv[0].x + xv[i].y * wv[1].x + xv[i].z * wv[2].x + xv[i].w * wv[3].x;
            acc[i].y += xv[i].x * wv[0].y + xv[i].y * wv[1].y + xv[i].z * wv[2].y + xv[i].w * wv[3].y;
            acc[i].z += xv[i].x * wv[0].z + xv[i].y * wv[1].z + xv[i].z * wv[2].z + xv[i].w * wv[3].z;
            acc[i].w += xv[i].x * wv[0].w + xv[i].y * wv[1].w + xv[i].z * wv[2].w + xv[i].w * wv[3].w;
        }
    }
}

template <int PASS>
__global__ __launch_bounds__(NTHREADS, 1)
void axial_attn_kernel(const float* __restrict__ x,
                       const float* __restrict__ Wq,
                       const float* __restrict__ Wkv,
                       const float* __restrict__ Wo,
                       const float* __restrict__ bo,
                       float* __restrict__ out)
{
    extern __shared__ float sm[];
    float* Xs = sm;            // X tile; overwritten with Q (scaled) after GEMMs
    float* Ks = sm + KS_OFF;
    float* Vs = sm + VS_OFF;
    float* Wc = sm + WC_OFF;

    const int t = threadIdx.x;
    const int seq = blockIdx.x;
    const int b   = seq >> 7;
    const int s   = seq & 127;
    const int base    = b * (128 * 128 * 128) + (PASS == 0 ? s * 128 : s * 16384);
    const int istride = (PASS == 0 ? 16384 : 128);

    // ---------------- Phase 1: load X tile ----------------
    {
        const int r  = t >> 1;
        const int hf = t & 1;
        const float* src = x + base + r * istride + hf * 64;
        float* dst = Xs + r * XSTRIDE + hf * 64;
        #pragma unroll
        for (int i = 0; i < 16; i++)
            reinterpret_cast<float4*>(dst)[i] = reinterpret_cast<const float4*>(src)[i];
    }

    // ---------------- Phase 2: K, V, Q projections ----------------
    const int cq = t & 7;    // col quad (4 cols) within 32-col chunk
    const int rg = t >> 3;   // row group: rows rg + 32*i

    // K then V
    #pragma unroll
    for (int kv = 0; kv < 2; kv++) {
        float* dstS = (kv == 0) ? Ks : Vs;
        for (int chunk = 0; chunk < 4; chunk++) {
            __syncthreads();
            #pragma unroll
            for (int i = 0; i < 16; i++) {
                int f = t + i * NTHREADS;
                Wc[f] = Wkv[(f >> 5) * 256 + kv * 128 + chunk * 32 + (f & 31)];
            }
            __syncthreads();
            float4 acc[4];
            gemm_chunk_4x4(Xs, Wc, rg, cq, acc);
            #pragma unroll
            for (int i = 0; i < 4; i++)
                *reinterpret_cast<float4*>(dstS + (rg + 32 * i) * XSTRIDE + chunk * 32 + cq * 4) = acc[i];
        }
    }

    // Q: accumulate all 4 chunks in registers (X must stay intact while any
    // thread still reads it), then overwrite X with scaled Q.
    float4 qacc[4][4];
    for (int chunk = 0; chunk < 4; chunk++) {
        __syncthreads();
        #pragma unroll
        for (int i = 0; i < 16; i++) {
            int f = t + i * NTHREADS;
            Wc[f] = Wq[(f >> 5) * 128 + chunk * 32 + (f & 31)];
        }
        __syncthreads();
        gemm_chunk_4x4(Xs, Wc, rg, cq, qacc[chunk]);
    }
    __syncthreads();   // all X reads complete
    #pragma unroll
    for (int chunk = 0; chunk < 4; chunk++)
        #pragma unroll
        for (int i = 0; i < 4; i++) {
            float4 v = qacc[chunk][i];
            v.x *= 0.25f; v.y *= 0.25f; v.z *= 0.25f; v.w *= 0.25f;  // 1/sqrt(16)
            *reinterpret_cast<float4*>(Xs + (rg + 32 * i) * XSTRIDE + chunk * 32 + cq * 4) = v;
        }

    // ---------------- Phase 3: attention + incremental out-proj ----------------
    // thread = (rp, qf): rows (2rp, 2rp+1); keys 4*jj+qf; out cols 16g+4qf.
    const int rp = t >> 2;
    const int qf = t & 3;
    const int r0 = 2 * rp;
    const int r1 = 2 * rp + 1;

    float y0[32], y1[32];
    #pragma unroll
    for (int c = 0; c < 32; c++) { y0[c] = 0.f; y1[c] = 0.f; }

    for (int h = 0; h < NHEADS; h++) {
        __syncthreads();   // Wc reuse; first iter: Q writes visible
        #pragma unroll
        for (int i = 0; i < 8; i++) {
            int f = t + i * NTHREADS;
            Wc[f] = Wo[(h * 16 + (f >> 7)) * 128 + (f & 127)];
        }
        __syncthreads();

        // load q for both rows (Q pre-scaled)
        float q0[16], q1[16];
        #pragma unroll
        for (int e4 = 0; e4 < 4; e4++) {
            float4 a = *reinterpret_cast<const float4*>(Xs + r0 * XSTRIDE + h * 16 + e4 * 4);
            float4 c = *reinterpret_cast<const float4*>(Xs + r1 * XSTRIDE + h * 16 + e4 * 4);
            q0[e4 * 4 + 0] = a.x; q0[e4 * 4 + 1] = a.y; q0[e4 * 4 + 2] = a.z; q0[e4 * 4 + 3] = a.w;
            q1[e4 * 4 + 0] = c.x; q1[e4 * 4 + 1] = c.y; q1[e4 * 4 + 2] = c.z; q1[e4 * 4 + 3] = c.w;
        }

        // dots for 32 interleaved keys, both rows
        float d0[32], d1[32];
        float m0 = -1e30f, m1 = -1e30f;
        #pragma unroll
        for (int jj = 0; jj < 32; jj++) {
            const float* kr = Ks + (4 * jj + qf) * XSTRIDE + h * 16;
            float s0 = 0.f, s1 = 0.f;
            #pragma unroll
            for (int e4 = 0; e4 < 4; e4++) {
                float4 k4 = *reinterpret_cast<const float4*>(kr + e4 * 4);
                s0 += q0[e4 * 4 + 0] * k4.x + q0[e4 * 4 + 1] * k4.y
                    + q0[e4 * 4 + 2] * k4.z + q0[e4 * 4 + 3] * k4.w;
                s1 += q1[e4 * 4 + 0] * k4.x + q1[e4 * 4 + 1] * k4.y
                    + q1[e4 * 4 + 2] * k4.z + q1[e4 * 4 + 3] * k4.w;
            }
            d0[jj] = s0; d1[jj] = s1;
            m0 = fmaxf(m0, s0); m1 = fmaxf(m1, s1);
        }
        m0 = fmaxf(m0, __shfl_xor_sync(0xffffffffu, m0, 1));
        m0 = fmaxf(m0, __shfl_xor_sync(0xffffffffu, m0, 2));
        m1 = fmaxf(m1, __shfl_xor_sync(0xffffffffu, m1, 1));
        m1 = fmaxf(m1, __shfl_xor_sync(0xffffffffu, m1, 2));

        // exp + sum + AV
        float oe0[16], oe1[16];
        #pragma unroll
        for (int e = 0; e < 16; e++) { oe0[e] = 0.f; oe1[e] = 0.f; }
        float l0 = 0.f, l1 = 0.f;
        #pragma unroll
        for (int jj = 0; jj < 32; jj++) {
            float p0 = __expf(d0[jj] - m0);
            float p1 = __expf(d1[jj] - m1);
            l0 += p0; l1 += p1;
            const float* vr = Vs + (4 * jj + qf) * XSTRIDE + h * 16;
            #pragma unroll
            for (int e4 = 0; e4 < 4; e4++) {
                float4 v4 = *reinterpret_cast<const float4*>(vr + e4 * 4);
                oe0[e4 * 4 + 0] += p0 * v4.x; oe0[e4 * 4 + 1] += p0 * v4.y;
                oe0[e4 * 4 + 2] += p0 * v4.z; oe0[e4 * 4 + 3] += p0 * v4.w;
                oe1[e4 * 4 + 0] += p1 * v4.x; oe1[e4 * 4 + 1] += p1 * v4.y;
                oe1[e4 * 4 + 2] += p1 * v4.z; oe1[e4 * 4 + 3] += p1 * v4.w;
            }
        }
        l0 += __shfl_xor_sync(0xffffffffu, l0, 1);
        l0 += __shfl_xor_sync(0xffffffffu, l0, 2);
        l1 += __shfl_xor_sync(0xffffffffu, l1, 1);
        l1 += __shfl_xor_sync(0xffffffffu, l1, 2);
        float inv0 = 1.0f / l0, inv1 = 1.0f / l1;
        #pragma unroll
        for (int e = 0; e < 16; e++) {
            oe0[e] += __shfl_xor_sync(0xffffffffu, oe0[e], 1);
            oe0[e] += __shfl_xor_sync(0xffffffffu, oe0[e], 2);
            oe0[e] *= inv0;
            oe1[e] += __shfl_xor_sync(0xffffffffu, oe1[e], 1);
            oe1[e] += __shfl_xor_sync(0xffffffffu, oe1[e], 2);
            oe1[e] *= inv1;
        }

        // out-proj: y[row][g*4+i] += sum_e oe[e] * Wo[e][16g + 4qf + i]
        #pragma unroll
        for (int e = 0; e < 16; e++) {
            float a0 = oe0[e], a1 = oe1[e];
            const float* wr = Wc + e * 128 + qf * 4;
            #pragma unroll
            for (int g = 0; g < 8; g++) {
                float4 w = *reinterpret_cast<const float4*>(wr + g * 16);
                y0[g * 4 + 0] += a0 * w.x; y0[g * 4 + 1] += a0 * w.y;
                y0[g * 4 + 2] += a0 * w.z; y0[g * 4 + 3] += a0 * w.w;
                y1[g * 4 + 0] += a1 * w.x; y1[g * 4 + 1] += a1 * w.y;
                y1[g * 4 + 2] += a1 * w.z; y1[g * 4 + 3] += a1 * w.w;
            }
        }
    }

    // ---------------- Phase 4: bias + write (pass1 accumulates) ----------------
    #pragma unroll
    for (int g = 0; g < 8; g++) {
        const int col = g * 16 + qf * 4;
        float4 bv = *reinterpret_cast<const float4*>(bo + col);
        float* op0 = out + base + r0 * istride + col;
        float* op1 = out + base + r1 * istride + col;
        float4 w0, w1;
        w0.x = y0[g * 4 + 0] + bv.x; w0.y = y0[g * 4 + 1] + bv.y;
        w0.z = y0[g * 4 + 2] + bv.z; w0.w = y0[g * 4 + 3] + bv.w;
        w1.x = y1[g * 4 + 0] + bv.x; w1.y = y1[g * 4 + 1] + bv.y;
        w1.z = y1[g * 4 + 2] + bv.z; w1.w = y1[g * 4 + 3] + bv.w;
        if (PASS == 1) {
            float4 p0 = *reinterpret_cast<const float4*>(op0);
            float4 p1 = *reinterpret_cast<const float4*>(op1);
            w0.x += p0.x; w0.y += p0.y; w0.z += p0.z; w0.w += p0.w;
            w1.x += p1.x; w1.y += p1.y; w1.z += p1.z; w1.w += p1.w;
        }
        *reinterpret_cast<float4*>(op0) = w0;
        *reinterpret_cast<float4*>(op1) = w1;
    }
}

extern "C" void kernel_launch(void* const* d_in, const int* in_sizes, int n_in,
                              void* d_out, int out_size)
{
    const float* x    = (const float*)d_in[0];
    const float* Wq0  = (const float*)d_in[1];
    const float* Wkv0 = (const float*)d_in[2];
    const float* Wo0  = (const float*)d_in[3];
    const float* bo0  = (const float*)d_in[4];
    const float* Wq1  = (const float*)d_in[5];
    const float* Wkv1 = (const float*)d_in[6];
    const float* Wo1  = (const float*)d_in[7];
    const float* bo1  = (const float*)d_in[8];
    float* out = (float*)d_out;

    cudaFuncSetAttribute(axial_attn_kernel<0>,
                         cudaFuncAttributeMaxDynamicSharedMemorySize, SMEM_BYTES);
    cudaFuncSetAttribute(axial_attn_kernel<1>,
                         cudaFuncAttributeMaxDynamicSharedMemorySize, SMEM_BYTES);

    axial_attn_kernel<0><<<1024, NTHREADS, SMEM_BYTES>>>(x, Wq0, Wkv0, Wo0, bo0, out);
    axial_attn_kernel<1><<<1024, NTHREADS, SMEM_BYTES>>>(x, Wq1, Wkv1, Wo1, bo1, out);
}

// round 8
// speedup vs baseline: 1.7062x; 1.1338x over previous
#include <cuda_runtime.h>
#include <cuda_fp16.h>
#include <cstdint>

// ---------------------------------------------------------------------------
// AxialAttention: x [8,128,128,128] fp32, 8 heads, head dim 16.
// Pass 0: attend along H; Pass 1: attend along W, accumulating into output.
// One CTA per sequence. Fully fused.
// R8 = R6 design, resubmitted (two broker-level container failures, zero
// kernel-side evidence; design audited: alignment/aliasing/barriers clean).
//  - Fused K/V/Q projection chunk loop: X row data loaded once for 3 GEMMs
//    (1.33 B/FMA vs 2.0), 48KB triple weight staging.
//  - K, V, Q, staged-Wo held in fp16 in smem (fp32 compute/accumulate):
//    halves phase-3 smem bytes. Error budget ~3e-4 << 1e-3.
// ---------------------------------------------------------------------------

#define NTHREADS 256
#define NHEADS   8
#define XSTRIDE  132   // fp32 X tile stride (floats)
#define HSTRIDE  136   // fp16 tile stride (halfs); 136*2=272B, 16B-aligned rows

static constexpr int KSH_F = 128 * XSTRIDE;            // 16896 floats
static constexpr int VSH_F = KSH_F + (128 * HSTRIDE) / 2;   // +8704
static constexpr int WC_F  = VSH_F + (128 * HSTRIDE) / 2;   // 34304
static constexpr int SMEM_FLOATS = WC_F + 3 * 4096;    // 46592
static constexpr int SMEM_BYTES  = SMEM_FLOATS * 4;    // 186,368 B

// Convert 16 contiguous halfs (16B-aligned) to 16 floats.
__device__ __forceinline__ void h16_to_f(const __half* p, float f[16])
{
    uint4 u0 = *reinterpret_cast<const uint4*>(p);
    uint4 u1 = *reinterpret_cast<const uint4*>(p + 8);
    const __half2* h0 = reinterpret_cast<const __half2*>(&u0);
    const __half2* h1 = reinterpret_cast<const __half2*>(&u1);
    #pragma unroll
    for (int i = 0; i < 4; i++) {
        float2 a = __half22float2(h0[i]); f[2 * i]     = a.x; f[2 * i + 1]     = a.y;
        float2 b = __half22float2(h1[i]); f[8 + 2 * i] = b.x; f[8 + 2 * i + 1] = b.y;
    }
}

template <int PASS>
__global__ __launch_bounds__(NTHREADS, 1)
void axial_attn_kernel(const float* __restrict__ x,
                       const float* __restrict__ Wq,
                       const float* __restrict__ Wkv,
                       const float* __restrict__ Wo,
                       const float* __restrict__ bo,
                       float* __restrict__ out)
{
    extern __shared__ float sm[];
    float*  Xs  = sm;                                   // fp32 X; later fp16 Q
    __half* Qh  = reinterpret_cast<__half*>(sm);        // overlays X after GEMMs
    __half* Ksh = reinterpret_cast<__half*>(sm + KSH_F);
    __half* Vsh = reinterpret_cast<__half*>(sm + VSH_F);
    float*  WcK = sm + WC_F;
    float*  WcV = WcK + 4096;
    float*  WcQ = WcK + 8192;
    __half* Woh = reinterpret_cast<__half*>(WcK);       // phase-3 reuse

    const int t = threadIdx.x;
    const int seq = blockIdx.x;
    const int b   = seq >> 7;
    const int s   = seq & 127;
    const int base    = b * (128 * 128 * 128) + (PASS == 0 ? s * 128 : s * 16384);
    const int istride = (PASS == 0 ? 16384 : 128);

    // ---------------- Phase 1: load X tile (fp32) ----------------
    {
        const int r  = t >> 1;
        const int hf = t & 1;
        const float* src = x + base + r * istride + hf * 64;
        float* dst = Xs + r * XSTRIDE + hf * 64;
        #pragma unroll
        for (int i = 0; i < 16; i++)
            reinterpret_cast<float4*>(dst)[i] = reinterpret_cast<const float4*>(src)[i];
    }

    // ---------------- Phase 2: fused K/V/Q projections ----------------
    // 4 chunks of 32 output cols; X rows loaded once per kb feed 3 GEMMs.
    const int cq = t & 7;    // col quad within chunk
    const int rg = t >> 3;   // row group: rows rg + 32*i

    float4 qacc[4][4];
    for (int chunk = 0; chunk < 4; chunk++) {
        __syncthreads();  // covers phase-1 / previous chunk consumers
        #pragma unroll
        for (int i = 0; i < 16; i++) {
            int f = t + i * NTHREADS;          // 0..4095
            int k = f >> 5, c = f & 31;
            WcK[f] = Wkv[k * 256 + chunk * 32 + c];
            WcV[f] = Wkv[k * 256 + 128 + chunk * 32 + c];
            WcQ[f] = Wq[k * 128 + chunk * 32 + c];
        }
        __syncthreads();

        float4 ka[4], va[4], qa[4];
        #pragma unroll
        for (int i = 0; i < 4; i++) {
            ka[i] = make_float4(0.f, 0.f, 0.f, 0.f);
            va[i] = make_float4(0.f, 0.f, 0.f, 0.f);
            qa[i] = make_float4(0.f, 0.f, 0.f, 0.f);
        }
        #pragma unroll 2
        for (int kb = 0; kb < 32; kb++) {
            float4 xt[4];
            #pragma unroll
            for (int i = 0; i < 4; i++)
                xt[i] = *reinterpret_cast<const float4*>(Xs + (rg + 32 * i) * XSTRIDE + kb * 4);
            float xr[4][4];
            #pragma unroll
            for (int i = 0; i < 4; i++) {
                xr[i][0] = xt[i].x; xr[i][1] = xt[i].y; xr[i][2] = xt[i].z; xr[i][3] = xt[i].w;
            }
            #pragma unroll
            for (int k2 = 0; k2 < 4; k2++) {
                float4 kw = *reinterpret_cast<const float4*>(WcK + (kb * 4 + k2) * 32 + cq * 4);
                float4 vw = *reinterpret_cast<const float4*>(WcV + (kb * 4 + k2) * 32 + cq * 4);
                float4 qw = *reinterpret_cast<const float4*>(WcQ + (kb * 4 + k2) * 32 + cq * 4);
                #pragma unroll
                for (int i = 0; i < 4; i++) {
                    float xs = xr[i][k2];
                    ka[i].x += xs * kw.x; ka[i].y += xs * kw.y; ka[i].z += xs * kw.z; ka[i].w += xs * kw.w;
                    va[i].x += xs * vw.x; va[i].y += xs * vw.y; va[i].z += xs * vw.z; va[i].w += xs * vw.w;
                    qa[i].x += xs * qw.x; qa[i].y += xs * qw.y; qa[i].z += xs * qw.z; qa[i].w += xs * qw.w;
                }
            }
        }
        // store K, V as fp16; hold Q in registers (X still live)
        #pragma unroll
        for (int i = 0; i < 4; i++) {
            const int off = (rg + 32 * i) * HSTRIDE + chunk * 32 + cq * 4;
            union { __half2 h[2]; uint2 u; } pk;
            pk.h[0] = __floats2half2_rn(ka[i].x, ka[i].y);
            pk.h[1] = __floats2half2_rn(ka[i].z, ka[i].w);
            *reinterpret_cast<uint2*>(Ksh + off) = pk.u;
            pk.h[0] = __floats2half2_rn(va[i].x, va[i].y);
            pk.h[1] = __floats2half2_rn(va[i].z, va[i].w);
            *reinterpret_cast<uint2*>(Vsh + off) = pk.u;
            qacc[chunk][i] = qa[i];
        }
    }
    __syncthreads();   // all X reads complete
    #pragma unroll
    for (int chunk = 0; chunk < 4; chunk++)
        #pragma unroll
        for (int i = 0; i < 4; i++) {
            float4 v = qacc[chunk][i];
            union { __half2 h[2]; uint2 u; } pk;
            pk.h[0] = __floats2half2_rn(v.x * 0.25f, v.y * 0.25f);   // 1/sqrt(16)
            pk.h[1] = __floats2half2_rn(v.z * 0.25f, v.w * 0.25f);
            *reinterpret_cast<uint2*>(Qh + (rg + 32 * i) * HSTRIDE + chunk * 32 + cq * 4) = pk.u;
        }

    // ---------------- Phase 3: attention + incremental out-proj ----------------
    // thread = (rp, qf): rows (2rp, 2rp+1); keys 4*jj+qf; out cols 16g+4qf.
    const int rp = t >> 2;
    const int qf = t & 3;
    const int r0 = 2 * rp;
    const int r1 = 2 * rp + 1;

    float y0[32], y1[32];
    #pragma unroll
    for (int c = 0; c < 32; c++) { y0[c] = 0.f; y1[c] = 0.f; }

    for (int h = 0; h < NHEADS; h++) {
        __syncthreads();   // Wc/Woh reuse; first iter: Q/K/V stores visible
        #pragma unroll
        for (int i = 0; i < 8; i++) {
            int f = t + i * NTHREADS;          // 0..2047
            Woh[f] = __float2half(Wo[(h * 16 + (f >> 7)) * 128 + (f & 127)]);
        }
        __syncthreads();

        float q0[16], q1[16];
        h16_to_f(Qh + r0 * HSTRIDE + h * 16, q0);
        h16_to_f(Qh + r1 * HSTRIDE + h * 16, q1);

        // dots for 32 interleaved keys, both rows
        float d0[32], d1[32];
        float m0 = -1e30f, m1 = -1e30f;
        #pragma unroll
        for (int jj = 0; jj < 32; jj++) {
            float kf[16];
            h16_to_f(Ksh + (4 * jj + qf) * HSTRIDE + h * 16, kf);
            float s0 = 0.f, s1 = 0.f;
            #pragma unroll
            for (int e = 0; e < 16; e++) {
                s0 += q0[e] * kf[e];
                s1 += q1[e] * kf[e];
            }
            d0[jj] = s0; d1[jj] = s1;
            m0 = fmaxf(m0, s0); m1 = fmaxf(m1, s1);
        }
        m0 = fmaxf(m0, __shfl_xor_sync(0xffffffffu, m0, 1));
        m0 = fmaxf(m0, __shfl_xor_sync(0xffffffffu, m0, 2));
        m1 = fmaxf(m1, __shfl_xor_sync(0xffffffffu, m1, 1));
        m1 = fmaxf(m1, __shfl_xor_sync(0xffffffffu, m1, 2));

        // exp + sum + AV
        float oe0[16], oe1[16];
        #pragma unroll
        for (int e = 0; e < 16; e++) { oe0[e] = 0.f; oe1[e] = 0.f; }
        float l0 = 0.f, l1 = 0.f;
        #pragma unroll
        for (int jj = 0; jj < 32; jj++) {
            float p0 = __expf(d0[jj] - m0);
            float p1 = __expf(d1[jj] - m1);
            l0 += p0; l1 += p1;
            float vf[16];
            h16_to_f(Vsh + (4 * jj + qf) * HSTRIDE + h * 16, vf);
            #pragma unroll
            for (int e = 0; e < 16; e++) {
                oe0[e] += p0 * vf[e];
                oe1[e] += p1 * vf[e];
            }
        }
        l0 += __shfl_xor_sync(0xffffffffu, l0, 1);
        l0 += __shfl_xor_sync(0xffffffffu, l0, 2);
        l1 += __shfl_xor_sync(0xffffffffu, l1, 1);
        l1 += __shfl_xor_sync(0xffffffffu, l1, 2);
        float inv0 = 1.0f / l0, inv1 = 1.0f / l1;
        #pragma unroll
        for (int e = 0; e < 16; e++) {
            oe0[e] += __shfl_xor_sync(0xffffffffu, oe0[e], 1);
            oe0[e] += __shfl_xor_sync(0xffffffffu, oe0[e], 2);
            oe0[e] *= inv0;
            oe1[e] += __shfl_xor_sync(0xffffffffu, oe1[e], 1);
            oe1[e] += __shfl_xor_sync(0xffffffffu, oe1[e], 2);
            oe1[e] *= inv1;
        }

        // out-proj: y[row][g*4+i] += sum_e oe[e] * Wo[e][16g + 4qf + i]
        #pragma unroll
        for (int e = 0; e < 16; e++) {
            float a0 = oe0[e], a1 = oe1[e];
            const __half* wr = Woh + e * 128 + qf * 4;
            #pragma unroll
            for (int g = 0; g < 8; g++) {
                uint2 w = *reinterpret_cast<const uint2*>(wr + g * 16);
                float2 w01 = __half22float2(*reinterpret_cast<const __half2*>(&w.x));
                float2 w23 = __half22float2(*reinterpret_cast<const __half2*>(&w.y));
                y0[g * 4 + 0] += a0 * w01.x; y0[g * 4 + 1] += a0 * w01.y;
                y0[g * 4 + 2] += a0 * w23.x; y0[g * 4 + 3] += a0 * w23.y;
                y1[g * 4 + 0] += a1 * w01.x; y1[g * 4 + 1] += a1 * w01.y;
                y1[g * 4 + 2] += a1 * w23.x; y1[g * 4 + 3] += a1 * w23.y;
            }
        }
    }

    // ---------------- Phase 4: bias + write (pass1 accumulates) ----------------
    #pragma unroll
    for (int g = 0; g < 8; g++) {
        const int col = g * 16 + qf * 4;
        float4 bv = *reinterpret_cast<const float4*>(bo + col);
        float* op0 = out + base + r0 * istride + col;
        float* op1 = out + base + r1 * istride + col;
        float4 w0, w1;
        w0.x = y0[g * 4 + 0] + bv.x; w0.y = y0[g * 4 + 1] + bv.y;
        w0.z = y0[g * 4 + 2] + bv.z; w0.w = y0[g * 4 + 3] + bv.w;
        w1.x = y1[g * 4 + 0] + bv.x; w1.y = y1[g * 4 + 1] + bv.y;
        w1.z = y1[g * 4 + 2] + bv.z; w1.w = y1[g * 4 + 3] + bv.w;
        if (PASS == 1) {
            float4 p0 = *reinterpret_cast<const float4*>(op0);
            float4 p1 = *reinterpret_cast<const float4*>(op1);
            w0.x += p0.x; w0.y += p0.y; w0.z += p0.z; w0.w += p0.w;
            w1.x += p1.x; w1.y += p1.y; w1.z += p1.z; w1.w += p1.w;
        }
        *reinterpret_cast<float4*>(op0) = w0;
        *reinterpret_cast<float4*>(op1) = w1;
    }
}

extern "C" void kernel_launch(void* const* d_in, const int* in_sizes, int n_in,
                              void* d_out, int out_size)
{
    const float* x    = (const float*)d_in[0];
    const float* Wq0  = (const float*)d_in[1];
    const float* Wkv0 = (const float*)d_in[2];
    const float* Wo0  = (const float*)d_in[3];
    const float* bo0  = (const float*)d_in[4];
    const float* Wq1  = (const float*)d_in[5];
    const float* Wkv1 = (const float*)d_in[6];
    const float* Wo1  = (const float*)d_in[7];
    const float* bo1  = (const float*)d_in[8];
    float* out = (float*)d_out;

    cudaFuncSetAttribute(axial_attn_kernel<0>,
                         cudaFuncAttributeMaxDynamicSharedMemorySize, SMEM_BYTES);
    cudaFuncSetAttribute(axial_attn_kernel<1>,
                         cudaFuncAttributeMaxDynamicSharedMemorySize, SMEM_BYTES);

    axial_attn_kernel<0><<<1024, NTHREADS, SMEM_BYTES>>>(x, Wq0, Wkv0, Wo0, bo0, out);
    axial_attn_kernel<1><<<1024, NTHREADS, SMEM_BYTES>>>(x, Wq1, Wkv1, Wo1, bo1, out);
}

// round 10
// speedup vs baseline: 5.1248x; 3.0036x over previous
#include <cuda_runtime.h>
#include <cuda_fp16.h>
#include <cstdint>

// ---------------------------------------------------------------------------
// AxialAttention via warp-level tensor cores (mma.sync m16n8k16 f16->f32).
// x [8,128,128,128] fp32. Pass 0 attends along H, pass 1 along W (accumulates).
// One CTA (256 thr = 8 warps) per 128x128 sequence; warp w owns rows 16w..16w+15.
// All GEMMs (K/V/Q proj, QK^T, PV, out-proj) on HMMA, fp32 accumulate.
// Q and P never touch smem: C-frag of producer GEMM == A-frag of consumer GEMM.
// R10 = R9 resubmission (broker container failure, no kernel evidence;
// fragment maps re-audited: A x4, B x2t/x2, C->A chaining all verified).
// ---------------------------------------------------------------------------

#define NTHREADS 256
#define HS 136                       // halfs per tile row (272B: ldmatrix conflict-free)
static constexpr int TILE   = 128 * HS;      // halfs per 128x128 tile
static constexpr int KH_O   = TILE;
static constexpr int VH_O   = 2 * TILE;
static constexpr int WK_O   = 3 * TILE;
static constexpr int WV_O   = 4 * TILE;
static constexpr int WQ_O   = 5 * TILE;
static constexpr int SMEM_BYTES = 6 * TILE * 2;   // 208,896 B

__device__ __forceinline__ uint32_t sptr(const void* p) {
    return (uint32_t)__cvta_generic_to_shared(p);
}
__device__ __forceinline__ void ldsm_x4(uint32_t r[4], uint32_t a) {
    asm volatile("ldmatrix.sync.aligned.m8n8.x4.shared.b16 {%0,%1,%2,%3}, [%4];"
                 : "=r"(r[0]), "=r"(r[1]), "=r"(r[2]), "=r"(r[3]) : "r"(a));
}
__device__ __forceinline__ void ldsm_x2(uint32_t& r0, uint32_t& r1, uint32_t a) {
    asm volatile("ldmatrix.sync.aligned.m8n8.x2.shared.b16 {%0,%1}, [%2];"
                 : "=r"(r0), "=r"(r1) : "r"(a));
}
__device__ __forceinline__ void ldsm_x2t(uint32_t& r0, uint32_t& r1, uint32_t a) {
    asm volatile("ldmatrix.sync.aligned.m8n8.x2.trans.shared.b16 {%0,%1}, [%2];"
                 : "=r"(r0), "=r"(r1) : "r"(a));
}
__device__ __forceinline__ void mma_f16(float c[4], const uint32_t a[4],
                                        uint32_t b0, uint32_t b1) {
    asm volatile(
        "mma.sync.aligned.m16n8k16.row.col.f32.f16.f16.f32 "
        "{%0,%1,%2,%3}, {%4,%5,%6,%7}, {%8,%9}, {%0,%1,%2,%3};"
        : "+f"(c[0]), "+f"(c[1]), "+f"(c[2]), "+f"(c[3])
        : "r"(a[0]), "r"(a[1]), "r"(a[2]), "r"(a[3]), "r"(b0), "r"(b1));
}
__device__ __forceinline__ uint32_t packh2(float a, float b) {
    __half2 h = __floats2half2_rn(a, b);
    return *reinterpret_cast<uint32_t*>(&h);
}
// Stage one 64-float half-row: fp32 global -> fp16 smem tile [r][hf*64 ..+63].
__device__ __forceinline__ void stage_row(__half* tile, const float* src, int r, int hf) {
    const float4* s4 = reinterpret_cast<const float4*>(src);
    uint4* d4 = reinterpret_cast<uint4*>(tile + r * HS + hf * 64);
    #pragma unroll
    for (int i = 0; i < 8; i++) {
        float4 a = s4[2 * i], c = s4[2 * i + 1];
        uint4 u;
        u.x = packh2(a.x, a.y); u.y = packh2(a.z, a.w);
        u.z = packh2(c.x, c.y); u.w = packh2(c.z, c.w);
        d4[i] = u;
    }
}

template <int PASS>
__global__ __launch_bounds__(NTHREADS, 1)
void axial_attn_kernel(const float* __restrict__ x,
                       const float* __restrict__ Wq,
                       const float* __restrict__ Wkv,
                       const float* __restrict__ Wo,
                       const float* __restrict__ bo,
                       float* __restrict__ out)
{
    extern __shared__ __half smh[];
    __half* Xh  = smh;             // X tile; reused as attention-out (Oa)
    __half* Kh  = smh + KH_O;
    __half* Vh  = smh + VH_O;
    __half* Wkh = smh + WK_O;      // K proj weights; reused for Wo
    __half* Wvh = smh + WV_O;
    __half* Wqh = smh + WQ_O;

    const int t    = threadIdx.x;
    const int w    = t >> 5;
    const int lane = t & 31;
    const int lr   = lane & 7;
    const int lg   = lane >> 3;          // ldmatrix group 0..3
    const int lq   = lane >> 2;          // C-frag row-in-8
    const int lc   = lane & 3;           // C-frag col pair
    const int m0   = w * 16;             // warp row strip

    const int seq = blockIdx.x;
    const int b   = seq >> 7;
    const int s   = seq & 127;
    const int base    = b * (128 * 128 * 128) + (PASS == 0 ? s * 128 : s * 16384);
    const int istride = (PASS == 0 ? 16384 : 128);

    // ---- Phase 1: stage X, Wk, Wv, Wq to fp16 smem ----
    {
        const int r = t >> 1, hf = t & 1;
        stage_row(Xh,  x   + base + r * istride + hf * 64, r, hf);
        stage_row(Wkh, Wkv + r * 256 + hf * 64,            r, hf);
        stage_row(Wvh, Wkv + r * 256 + 128 + hf * 64,      r, hf);
        stage_row(Wqh, Wq  + r * 128 + hf * 64,            r, hf);
    }
    __syncthreads();

    // A-frag base address for this warp's 16-row strip (Xh, later Oa)
    const uint32_t xaddr = sptr(Xh + (m0 + lr + ((lg & 1) << 3)) * HS + ((lg >> 1) << 3));
    // B-trans row offset within a 16-k block (weights / V)
    const int wrow = ((lg & 1) << 3) + lr;

    // Preload X A-fragments: 8 k-blocks
    uint32_t xa[8][4];
    #pragma unroll
    for (int kb = 0; kb < 8; kb++) ldsm_x4(xa[kb], xaddr + kb * 32);

    // ---- Phase 2: projections (tensor cores) ----
    uint32_t qreg[16][2];   // Q C-frags as half2, pre-scaled: A-frags for QK^T
    #pragma unroll
    for (int nt = 0; nt < 16; nt++) {   // K
        float c[4] = {0.f, 0.f, 0.f, 0.f};
        #pragma unroll
        for (int kb = 0; kb < 8; kb++) {
            uint32_t b0, b1;
            ldsm_x2t(b0, b1, sptr(Wkh + (kb * 16 + wrow) * HS + nt * 8));
            mma_f16(c, xa[kb], b0, b1);
        }
        *reinterpret_cast<uint32_t*>(Kh + (m0 + lq)     * HS + nt * 8 + 2 * lc) = packh2(c[0], c[1]);
        *reinterpret_cast<uint32_t*>(Kh + (m0 + lq + 8) * HS + nt * 8 + 2 * lc) = packh2(c[2], c[3]);
    }
    #pragma unroll
    for (int nt = 0; nt < 16; nt++) {   // V
        float c[4] = {0.f, 0.f, 0.f, 0.f};
        #pragma unroll
        for (int kb = 0; kb < 8; kb++) {
            uint32_t b0, b1;
            ldsm_x2t(b0, b1, sptr(Wvh + (kb * 16 + wrow) * HS + nt * 8));
            mma_f16(c, xa[kb], b0, b1);
        }
        *reinterpret_cast<uint32_t*>(Vh + (m0 + lq)     * HS + nt * 8 + 2 * lc) = packh2(c[0], c[1]);
        *reinterpret_cast<uint32_t*>(Vh + (m0 + lq + 8) * HS + nt * 8 + 2 * lc) = packh2(c[2], c[3]);
    }
    #pragma unroll
    for (int nt = 0; nt < 16; nt++) {   // Q (kept in registers, scale folded)
        float c[4] = {0.f, 0.f, 0.f, 0.f};
        #pragma unroll
        for (int kb = 0; kb < 8; kb++) {
            uint32_t b0, b1;
            ldsm_x2t(b0, b1, sptr(Wqh + (kb * 16 + wrow) * HS + nt * 8));
            mma_f16(c, xa[kb], b0, b1);
        }
        qreg[nt][0] = packh2(c[0] * 0.25f, c[1] * 0.25f);   // 1/sqrt(16)
        qreg[nt][1] = packh2(c[2] * 0.25f, c[3] * 0.25f);
    }
    __syncthreads();   // Kh/Vh visible to all warps; Wkh reads complete

    // ---- Stage Wo into Wkh space ----
    {
        const int r = t >> 1, hf = t & 1;
        stage_row(Wkh, Wo + r * 128 + hf * 64, r, hf);
    }
    __syncthreads();

    // ---- Phase 3: attention (per head); Oa written into Xh (own strip only) ----
    for (int h = 0; h < 8; h++) {
        const uint32_t A[4] = { qreg[2 * h][0], qreg[2 * h][1],
                                qreg[2 * h + 1][0], qreg[2 * h + 1][1] };
        float sf[16][4];
        #pragma unroll
        for (int nt = 0; nt < 16; nt++) {
            uint32_t b0, b1;
            ldsm_x2(b0, b1, sptr(Kh + (nt * 8 + lr) * HS + h * 16 + ((lg & 1) << 3)));
            sf[nt][0] = sf[nt][1] = sf[nt][2] = sf[nt][3] = 0.f;
            mma_f16(sf[nt], A, b0, b1);
        }
        // softmax over 128 keys; rows lq (c0,c1) and lq+8 (c2,c3)
        float mx0 = -1e30f, mx1 = -1e30f;
        #pragma unroll
        for (int nt = 0; nt < 16; nt++) {
            mx0 = fmaxf(mx0, fmaxf(sf[nt][0], sf[nt][1]));
            mx1 = fmaxf(mx1, fmaxf(sf[nt][2], sf[nt][3]));
        }
        mx0 = fmaxf(mx0, __shfl_xor_sync(0xffffffffu, mx0, 1));
        mx0 = fmaxf(mx0, __shfl_xor_sync(0xffffffffu, mx0, 2));
        mx1 = fmaxf(mx1, __shfl_xor_sync(0xffffffffu, mx1, 1));
        mx1 = fmaxf(mx1, __shfl_xor_sync(0xffffffffu, mx1, 2));
        float l0 = 0.f, l1 = 0.f;
        #pragma unroll
        for (int nt = 0; nt < 16; nt++) {
            float e0 = __expf(sf[nt][0] - mx0), e1 = __expf(sf[nt][1] - mx0);
            float e2 = __expf(sf[nt][2] - mx1), e3 = __expf(sf[nt][3] - mx1);
            sf[nt][0] = e0; sf[nt][1] = e1; sf[nt][2] = e2; sf[nt][3] = e3;
            l0 += e0 + e1; l1 += e2 + e3;
        }
        l0 += __shfl_xor_sync(0xffffffffu, l0, 1);
        l0 += __shfl_xor_sync(0xffffffffu, l0, 2);
        l1 += __shfl_xor_sync(0xffffffffu, l1, 1);
        l1 += __shfl_xor_sync(0xffffffffu, l1, 2);

        // P (fp16, from S frags) @ V
        float o0[4] = {0.f, 0.f, 0.f, 0.f}, o1[4] = {0.f, 0.f, 0.f, 0.f};
        #pragma unroll
        for (int kb = 0; kb < 8; kb++) {
            const uint32_t pa[4] = {
                packh2(sf[2 * kb][0],     sf[2 * kb][1]),
                packh2(sf[2 * kb][2],     sf[2 * kb][3]),
                packh2(sf[2 * kb + 1][0], sf[2 * kb + 1][1]),
                packh2(sf[2 * kb + 1][2], sf[2 * kb + 1][3]) };
            uint32_t b0, b1;
            ldsm_x2t(b0, b1, sptr(Vh + (kb * 16 + wrow) * HS + h * 16));
            mma_f16(o0, pa, b0, b1);
            ldsm_x2t(b0, b1, sptr(Vh + (kb * 16 + wrow) * HS + h * 16 + 8));
            mma_f16(o1, pa, b0, b1);
        }
        const float i0 = 1.0f / l0, i1 = 1.0f / l1;
        *reinterpret_cast<uint32_t*>(Xh + (m0 + lq)     * HS + h * 16 +     2 * lc) = packh2(o0[0] * i0, o0[1] * i0);
        *reinterpret_cast<uint32_t*>(Xh + (m0 + lq + 8) * HS + h * 16 +     2 * lc) = packh2(o0[2] * i1, o0[3] * i1);
        *reinterpret_cast<uint32_t*>(Xh + (m0 + lq)     * HS + h * 16 + 8 + 2 * lc) = packh2(o1[0] * i0, o1[1] * i0);
        *reinterpret_cast<uint32_t*>(Xh + (m0 + lq + 8) * HS + h * 16 + 8 + 2 * lc) = packh2(o1[2] * i1, o1[3] * i1);
    }
    // No barrier: each warp reads back only its own Oa strip.

    // ---- Phase 4: out-projection + bias (+pass1 accumulate) ----
    uint32_t oa[8][4];
    #pragma unroll
    for (int kb = 0; kb < 8; kb++) ldsm_x4(oa[kb], xaddr + kb * 32);
    #pragma unroll
    for (int nt = 0; nt < 16; nt++) {
        float c[4] = {0.f, 0.f, 0.f, 0.f};
        #pragma unroll
        for (int kb = 0; kb < 8; kb++) {
            uint32_t b0, b1;
            ldsm_x2t(b0, b1, sptr(Wkh + (kb * 16 + wrow) * HS + nt * 8));
            mma_f16(c, oa[kb], b0, b1);
        }
        const int col = nt * 8 + 2 * lc;
        const float2 bv = *reinterpret_cast<const float2*>(bo + col);
        float* p0 = out + base + (m0 + lq)     * istride + col;
        float* p1 = out + base + (m0 + lq + 8) * istride + col;
        float2 w0 = make_float2(c[0] + bv.x, c[1] + bv.y);
        float2 w1 = make_float2(c[2] + bv.x, c[3] + bv.y);
        if (PASS == 1) {
            float2 q0 = *reinterpret_cast<const float2*>(p0);
            float2 q1 = *reinterpret_cast<const float2*>(p1);
            w0.x += q0.x; w0.y += q0.y;
            w1.x += q1.x; w1.y += q1.y;
        }
        *reinterpret_cast<float2*>(p0) = w0;
        *reinterpret_cast<float2*>(p1) = w1;
    }
}

extern "C" void kernel_launch(void* const* d_in, const int* in_sizes, int n_in,
                              void* d_out, int out_size)
{
    const float* x    = (const float*)d_in[0];
    const float* Wq0  = (const float*)d_in[1];
    const float* Wkv0 = (const float*)d_in[2];
    const float* Wo0  = (const float*)d_in[3];
    const float* bo0  = (const float*)d_in[4];
    const float* Wq1  = (const float*)d_in[5];
    const float* Wkv1 = (const float*)d_in[6];
    const float* Wo1  = (const float*)d_in[7];
    const float* bo1  = (const float*)d_in[8];
    float* out = (float*)d_out;

    cudaFuncSetAttribute(axial_attn_kernel<0>,
                         cudaFuncAttributeMaxDynamicSharedMemorySize, SMEM_BYTES);
    cudaFuncSetAttribute(axial_attn_kernel<1>,
                         cudaFuncAttributeMaxDynamicSharedMemorySize, SMEM_BYTES);

    axial_attn_kernel<0><<<1024, NTHREADS, SMEM_BYTES>>>(x, Wq0, Wkv0, Wo0, bo0, out);
    axial_attn_kernel<1><<<1024, NTHREADS, SMEM_BYTES>>>(x, Wq1, Wkv1, Wo1, bo1, out);
}

// round 11
// speedup vs baseline: 5.9622x; 1.1634x over previous
#include <cuda_runtime.h>
#include <cuda_fp16.h>
#include <cstdint>

// ---------------------------------------------------------------------------
// AxialAttention via warp-level tensor cores (mma.sync m16n8k16 f16->f32).
// R11: occupancy push. 3 smem tiles (104.4 KB) -> 2 CTAs/SM; launch_bounds
// (256,2); S-fragments packed fp16 (sp[16][2]) to fit 128 regs.
//   T0: X -> Wk -> Wv -> Wq -> Wo (serial staging, barriers)
//   T1: K -> Oa (Oa overwrites spent K columns per head; barrier per head)
//   T2: V
// ---------------------------------------------------------------------------

#define NTHREADS 256
#define HS 136                       // halfs per tile row (272B: ldmatrix conflict-free)
static constexpr int TILE = 128 * HS;
static constexpr int SMEM_BYTES = 3 * TILE * 2;   // 104,448 B -> 2 CTAs/SM

__device__ __forceinline__ uint32_t sptr(const void* p) {
    return (uint32_t)__cvta_generic_to_shared(p);
}
__device__ __forceinline__ void ldsm_x4(uint32_t r[4], uint32_t a) {
    asm volatile("ldmatrix.sync.aligned.m8n8.x4.shared.b16 {%0,%1,%2,%3}, [%4];"
                 : "=r"(r[0]), "=r"(r[1]), "=r"(r[2]), "=r"(r[3]) : "r"(a));
}
__device__ __forceinline__ void ldsm_x2(uint32_t& r0, uint32_t& r1, uint32_t a) {
    asm volatile("ldmatrix.sync.aligned.m8n8.x2.shared.b16 {%0,%1}, [%2];"
                 : "=r"(r0), "=r"(r1) : "r"(a));
}
__device__ __forceinline__ void ldsm_x2t(uint32_t& r0, uint32_t& r1, uint32_t a) {
    asm volatile("ldmatrix.sync.aligned.m8n8.x2.trans.shared.b16 {%0,%1}, [%2];"
                 : "=r"(r0), "=r"(r1) : "r"(a));
}
__device__ __forceinline__ void mma_f16(float c[4], const uint32_t a[4],
                                        uint32_t b0, uint32_t b1) {
    asm volatile(
        "mma.sync.aligned.m16n8k16.row.col.f32.f16.f16.f32 "
        "{%0,%1,%2,%3}, {%4,%5,%6,%7}, {%8,%9}, {%0,%1,%2,%3};"
        : "+f"(c[0]), "+f"(c[1]), "+f"(c[2]), "+f"(c[3])
        : "r"(a[0]), "r"(a[1]), "r"(a[2]), "r"(a[3]), "r"(b0), "r"(b1));
}
__device__ __forceinline__ uint32_t packh2(float a, float b) {
    __half2 h = __floats2half2_rn(a, b);
    return *reinterpret_cast<uint32_t*>(&h);
}
__device__ __forceinline__ float2 unpackh2(uint32_t u) {
    __half2 h = *reinterpret_cast<__half2*>(&u);
    return __half22float2(h);
}
// Stage one 64-float half-row: fp32 global -> fp16 smem tile [r][hf*64 ..+63].
__device__ __forceinline__ void stage_row(__half* tile, const float* src, int r, int hf) {
    const float4* s4 = reinterpret_cast<const float4*>(src);
    uint4* d4 = reinterpret_cast<uint4*>(tile + r * HS + hf * 64);
    #pragma unroll
    for (int i = 0; i < 8; i++) {
        float4 a = s4[2 * i], c = s4[2 * i + 1];
        uint4 u;
        u.x = packh2(a.x, a.y); u.y = packh2(a.z, a.w);
        u.z = packh2(c.x, c.y); u.w = packh2(c.z, c.w);
        d4[i] = u;
    }
}

template <int PASS>
__global__ __launch_bounds__(NTHREADS, 2)
void axial_attn_kernel(const float* __restrict__ x,
                       const float* __restrict__ Wq,
                       const float* __restrict__ Wkv,
                       const float* __restrict__ Wo,
                       const float* __restrict__ bo,
                       float* __restrict__ out)
{
    extern __shared__ __half smh[];
    __half* T0 = smh;              // X -> Wk -> Wv -> Wq -> Wo
    __half* T1 = smh + TILE;       // K -> Oa
    __half* T2 = smh + 2 * TILE;   // V

    const int t    = threadIdx.x;
    const int w    = t >> 5;
    const int lane = t & 31;
    const int lr   = lane & 7;
    const int lg   = lane >> 3;          // ldmatrix group 0..3
    const int lq   = lane >> 2;          // C-frag row-in-8
    const int lc   = lane & 3;           // C-frag col pair
    const int m0   = w * 16;             // warp row strip

    const int seq = blockIdx.x;
    const int bb  = seq >> 7;
    const int s   = seq & 127;
    const int base    = bb * (128 * 128 * 128) + (PASS == 0 ? s * 128 : s * 16384);
    const int istride = (PASS == 0 ? 16384 : 128);

    const int sr = t >> 1, shf = t & 1;   // staging row / half

    // ---- Stage X into T0 ----
    stage_row(T0, x + base + sr * istride + shf * 64, sr, shf);
    __syncthreads();

    const uint32_t aoff  = (m0 + lr + ((lg & 1) << 3)) * HS + ((lg >> 1) << 3);
    const uint32_t xaddr = sptr(T0 + aoff);
    const uint32_t oaddr = sptr(T1 + aoff);
    const int wrow = ((lg & 1) << 3) + lr;     // B-trans row within 16-k block

    // X A-fragments (live through the three projection GEMMs)
    uint32_t xa[8][4];
    #pragma unroll
    for (int kb = 0; kb < 8; kb++) ldsm_x4(xa[kb], xaddr + kb * 32);
    __syncthreads();   // T0 free for weights

    // ---- K projection ----
    stage_row(T0, Wkv + sr * 256 + shf * 64, sr, shf);
    __syncthreads();
    #pragma unroll
    for (int nt = 0; nt < 16; nt++) {
        float c[4] = {0.f, 0.f, 0.f, 0.f};
        #pragma unroll
        for (int kb = 0; kb < 8; kb++) {
            uint32_t b0, b1;
            ldsm_x2t(b0, b1, sptr(T0 + (kb * 16 + wrow) * HS + nt * 8));
            mma_f16(c, xa[kb], b0, b1);
        }
        *reinterpret_cast<uint32_t*>(T1 + (m0 + lq)     * HS + nt * 8 + 2 * lc) = packh2(c[0], c[1]);
        *reinterpret_cast<uint32_t*>(T1 + (m0 + lq + 8) * HS + nt * 8 + 2 * lc) = packh2(c[2], c[3]);
    }
    __syncthreads();

    // ---- V projection ----
    stage_row(T0, Wkv + sr * 256 + 128 + shf * 64, sr, shf);
    __syncthreads();
    #pragma unroll
    for (int nt = 0; nt < 16; nt++) {
        float c[4] = {0.f, 0.f, 0.f, 0.f};
        #pragma unroll
        for (int kb = 0; kb < 8; kb++) {
            uint32_t b0, b1;
            ldsm_x2t(b0, b1, sptr(T0 + (kb * 16 + wrow) * HS + nt * 8));
            mma_f16(c, xa[kb], b0, b1);
        }
        *reinterpret_cast<uint32_t*>(T2 + (m0 + lq)     * HS + nt * 8 + 2 * lc) = packh2(c[0], c[1]);
        *reinterpret_cast<uint32_t*>(T2 + (m0 + lq + 8) * HS + nt * 8 + 2 * lc) = packh2(c[2], c[3]);
    }
    __syncthreads();

    // ---- Q projection (registers only; scale folded) ----
    stage_row(T0, Wq + sr * 128 + shf * 64, sr, shf);
    __syncthreads();
    uint32_t qreg[16][2];
    #pragma unroll
    for (int nt = 0; nt < 16; nt++) {
        float c[4] = {0.f, 0.f, 0.f, 0.f};
        #pragma unroll
        for (int kb = 0; kb < 8; kb++) {
            uint32_t b0, b1;
            ldsm_x2t(b0, b1, sptr(T0 + (kb * 16 + wrow) * HS + nt * 8));
            mma_f16(c, xa[kb], b0, b1);
        }
        qreg[nt][0] = packh2(c[0] * 0.25f, c[1] * 0.25f);   // 1/sqrt(16)
        qreg[nt][1] = packh2(c[2] * 0.25f, c[3] * 0.25f);
    }
    __syncthreads();

    // ---- Stage Wo into T0 (read-only through phases 3-4) ----
    stage_row(T0, Wo + sr * 128 + shf * 64, sr, shf);
    __syncthreads();

    // ---- Phase 3: attention; Oa overwrites spent K columns in T1 ----
    for (int h = 0; h < 8; h++) {
        uint32_t sp[16][2];               // S then P, packed fp16
        float mx0 = -1e30f, mx1 = -1e30f;
        #pragma unroll
        for (int nt = 0; nt < 16; nt++) {
            float c[4] = {0.f, 0.f, 0.f, 0.f};
            uint32_t b0, b1;
            ldsm_x2(b0, b1, sptr(T1 + (nt * 8 + lr) * HS + h * 16 + ((lg & 1) << 3)));
            mma_f16(c, qreg[2 * h], b0, b1);
            mx0 = fmaxf(mx0, fmaxf(c[0], c[1]));
            mx1 = fmaxf(mx1, fmaxf(c[2], c[3]));
            sp[nt][0] = packh2(c[0], c[1]);
            sp[nt][1] = packh2(c[2], c[3]);
        }
        __syncthreads();   // all warps' S reads of K cols h*16 complete before Oa writes

        mx0 = fmaxf(mx0, __shfl_xor_sync(0xffffffffu, mx0, 1));
        mx0 = fmaxf(mx0, __shfl_xor_sync(0xffffffffu, mx0, 2));
        mx1 = fmaxf(mx1, __shfl_xor_sync(0xffffffffu, mx1, 1));
        mx1 = fmaxf(mx1, __shfl_xor_sync(0xffffffffu, mx1, 2));

        float l0 = 0.f, l1 = 0.f;
        #pragma unroll
        for (int nt = 0; nt < 16; nt++) {
            float2 a = unpackh2(sp[nt][0]);
            float2 b = unpackh2(sp[nt][1]);
            float e0 = __expf(a.x - mx0), e1 = __expf(a.y - mx0);
            float e2 = __expf(b.x - mx1), e3 = __expf(b.y - mx1);
            l0 += e0 + e1; l1 += e2 + e3;
            sp[nt][0] = packh2(e0, e1);
            sp[nt][1] = packh2(e2, e3);
        }
        l0 += __shfl_xor_sync(0xffffffffu, l0, 1);
        l0 += __shfl_xor_sync(0xffffffffu, l0, 2);
        l1 += __shfl_xor_sync(0xffffffffu, l1, 1);
        l1 += __shfl_xor_sync(0xffffffffu, l1, 2);

        // P @ V
        float o0[4] = {0.f, 0.f, 0.f, 0.f}, o1[4] = {0.f, 0.f, 0.f, 0.f};
        #pragma unroll
        for (int kb = 0; kb < 8; kb++) {
            uint32_t b0, b1;
            ldsm_x2t(b0, b1, sptr(T2 + (kb * 16 + wrow) * HS + h * 16));
            mma_f16(o0, sp[2 * kb], b0, b1);
            ldsm_x2t(b0, b1, sptr(T2 + (kb * 16 + wrow) * HS + h * 16 + 8));
            mma_f16(o1, sp[2 * kb], b0, b1);
        }
        const float i0 = 1.0f / l0, i1 = 1.0f / l1;
        *reinterpret_cast<uint32_t*>(T1 + (m0 + lq)     * HS + h * 16 +     2 * lc) = packh2(o0[0] * i0, o0[1] * i0);
        *reinterpret_cast<uint32_t*>(T1 + (m0 + lq + 8) * HS + h * 16 +     2 * lc) = packh2(o0[2] * i1, o0[3] * i1);
        *reinterpret_cast<uint32_t*>(T1 + (m0 + lq)     * HS + h * 16 + 8 + 2 * lc) = packh2(o1[0] * i0, o1[1] * i0);
        *reinterpret_cast<uint32_t*>(T1 + (m0 + lq + 8) * HS + h * 16 + 8 + 2 * lc) = packh2(o1[2] * i1, o1[3] * i1);
    }
    __syncwarp();   // own-strip Oa stores visible to own warp's ldmatrix

    // ---- Phase 4: out-projection + bias (+pass1 accumulate) ----
    #pragma unroll
    for (int kb = 0; kb < 8; kb++) ldsm_x4(xa[kb], oaddr + kb * 32);   // reuse xa as oa
    #pragma unroll
    for (int nt = 0; nt < 16; nt++) {
        float c[4] = {0.f, 0.f, 0.f, 0.f};
        #pragma unroll
        for (int kb = 0; kb < 8; kb++) {
            uint32_t b0, b1;
            ldsm_x2t(b0, b1, sptr(T0 + (kb * 16 + wrow) * HS + nt * 8));
            mma_f16(c, xa[kb], b0, b1);
        }
        const int col = nt * 8 + 2 * lc;
        const float2 bv = *reinterpret_cast<const float2*>(bo + col);
        float* p0 = out + base + (m0 + lq)     * istride + col;
        float* p1 = out + base + (m0 + lq + 8) * istride + col;
        float2 w0 = make_float2(c[0] + bv.x, c[1] + bv.y);
        float2 w1 = make_float2(c[2] + bv.x, c[3] + bv.y);
        if (PASS == 1) {
            float2 q0 = *reinterpret_cast<const float2*>(p0);
            float2 q1 = *reinterpret_cast<const float2*>(p1);
            w0.x += q0.x; w0.y += q0.y;
            w1.x += q1.x; w1.y += q1.y;
        }
        *reinterpret_cast<float2*>(p0) = w0;
        *reinterpret_cast<float2*>(p1) = w1;
    }
}

extern "C" void kernel_launch(void* const* d_in, const int* in_sizes, int n_in,
                              void* d_out, int out_size)
{
    const float* x    = (const float*)d_in[0];
    const float* Wq0  = (const float*)d_in[1];
    const float* Wkv0 = (const float*)d_in[2];
    const float* Wo0  = (const float*)d_in[3];
    const float* bo0  = (const float*)d_in[4];
    const float* Wq1  = (const float*)d_in[5];
    const float* Wkv1 = (const float*)d_in[6];
    const float* Wo1  = (const float*)d_in[7];
    const float* bo1  = (const float*)d_in[8];
    float* out = (float*)d_out;

    cudaFuncSetAttribute(axial_attn_kernel<0>,
                         cudaFuncAttributeMaxDynamicSharedMemorySize, SMEM_BYTES);
    cudaFuncSetAttribute(axial_attn_kernel<1>,
                         cudaFuncAttributeMaxDynamicSharedMemorySize, SMEM_BYTES);

    axial_attn_kernel<0><<<1024, NTHREADS, SMEM_BYTES>>>(x, Wq0, Wkv0, Wo0, bo0, out);
    axial_attn_kernel<1><<<1024, NTHREADS, SMEM_BYTES>>>(x, Wq1, Wkv1, Wo1, bo1, out);
}

// round 12
// speedup vs baseline: 6.1230x; 1.0270x over previous
#include <cuda_runtime.h>
#include <cuda_fp16.h>
#include <cstdint>

// ---------------------------------------------------------------------------
// AxialAttention via warp-level tensor cores (mma.sync m16n8k16 f16->f32).
// R12: barrier-free attention. Oa lives in registers (PV C-frag == out-proj
// A-frag chaining), so phase 3 has ZERO CTA barriers and K is never
// overwritten. 3 smem tiles, 2 CTAs/SM, 128-reg cap.
//   T0: X -> Wk -> Wv -> Wq -> Wo (serial staging)
//   T1: K (read-only after projection)
//   T2: V
// ---------------------------------------------------------------------------

#define NTHREADS 256
#define HS 136                       // halfs per tile row (272B: ldmatrix conflict-free)
static constexpr int TILE = 128 * HS;
static constexpr int SMEM_BYTES = 3 * TILE * 2;   // 104,448 B -> 2 CTAs/SM

__device__ __forceinline__ uint32_t sptr(const void* p) {
    return (uint32_t)__cvta_generic_to_shared(p);
}
__device__ __forceinline__ void ldsm_x4(uint32_t r[4], uint32_t a) {
    asm volatile("ldmatrix.sync.aligned.m8n8.x4.shared.b16 {%0,%1,%2,%3}, [%4];"
                 : "=r"(r[0]), "=r"(r[1]), "=r"(r[2]), "=r"(r[3]) : "r"(a));
}
__device__ __forceinline__ void ldsm_x2(uint32_t& r0, uint32_t& r1, uint32_t a) {
    asm volatile("ldmatrix.sync.aligned.m8n8.x2.shared.b16 {%0,%1}, [%2];"
                 : "=r"(r0), "=r"(r1) : "r"(a));
}
__device__ __forceinline__ void ldsm_x2t(uint32_t& r0, uint32_t& r1, uint32_t a) {
    asm volatile("ldmatrix.sync.aligned.m8n8.x2.trans.shared.b16 {%0,%1}, [%2];"
                 : "=r"(r0), "=r"(r1) : "r"(a));
}
__device__ __forceinline__ void mma_f16(float c[4], const uint32_t a[4],
                                        uint32_t b0, uint32_t b1) {
    asm volatile(
        "mma.sync.aligned.m16n8k16.row.col.f32.f16.f16.f32 "
        "{%0,%1,%2,%3}, {%4,%5,%6,%7}, {%8,%9}, {%0,%1,%2,%3};"
        : "+f"(c[0]), "+f"(c[1]), "+f"(c[2]), "+f"(c[3])
        : "r"(a[0]), "r"(a[1]), "r"(a[2]), "r"(a[3]), "r"(b0), "r"(b1));
}
__device__ __forceinline__ uint32_t packh2(float a, float b) {
    __half2 h = __floats2half2_rn(a, b);
    return *reinterpret_cast<uint32_t*>(&h);
}
__device__ __forceinline__ float2 unpackh2(uint32_t u) {
    __half2 h = *reinterpret_cast<__half2*>(&u);
    return __half22float2(h);
}
// Stage one 64-float half-row: fp32 global -> fp16 smem tile [r][hf*64 ..+63].
__device__ __forceinline__ void stage_row(__half* tile, const float* src, int r, int hf) {
    const float4* s4 = reinterpret_cast<const float4*>(src);
    uint4* d4 = reinterpret_cast<uint4*>(tile + r * HS + hf * 64);
    #pragma unroll
    for (int i = 0; i < 8; i++) {
        float4 a = s4[2 * i], c = s4[2 * i + 1];
        uint4 u;
        u.x = packh2(a.x, a.y); u.y = packh2(a.z, a.w);
        u.z = packh2(c.x, c.y); u.w = packh2(c.z, c.w);
        d4[i] = u;
    }
}

template <int PASS>
__global__ __launch_bounds__(NTHREADS, 2)
void axial_attn_kernel(const float* __restrict__ x,
                       const float* __restrict__ Wq,
                       const float* __restrict__ Wkv,
                       const float* __restrict__ Wo,
                       const float* __restrict__ bo,
                       float* __restrict__ out)
{
    extern __shared__ __half smh[];
    __half* T0 = smh;              // X -> Wk -> Wv -> Wq -> Wo
    __half* T1 = smh + TILE;       // K (read-only after projection)
    __half* T2 = smh + 2 * TILE;   // V

    const int t    = threadIdx.x;
    const int w    = t >> 5;
    const int lane = t & 31;
    const int lr   = lane & 7;
    const int lg   = lane >> 3;          // ldmatrix group 0..3
    const int lq   = lane >> 2;          // C-frag row-in-8
    const int lc   = lane & 3;           // C-frag col pair
    const int m0   = w * 16;             // warp row strip

    const int seq = blockIdx.x;
    const int bb  = seq >> 7;
    const int s   = seq & 127;
    const int base    = bb * (128 * 128 * 128) + (PASS == 0 ? s * 128 : s * 16384);
    const int istride = (PASS == 0 ? 16384 : 128);

    const int sr = t >> 1, shf = t & 1;   // staging row / half

    // ---- Stage X into T0 ----
    stage_row(T0, x + base + sr * istride + shf * 64, sr, shf);
    __syncthreads();

    const uint32_t aoff  = (m0 + lr + ((lg & 1) << 3)) * HS + ((lg >> 1) << 3);
    const uint32_t xaddr = sptr(T0 + aoff);
    const int wrow = ((lg & 1) << 3) + lr;     // B-trans row within 16-k block

    // X A-fragments (live through the three projection GEMMs)
    uint32_t xa[8][4];
    #pragma unroll
    for (int kb = 0; kb < 8; kb++) ldsm_x4(xa[kb], xaddr + kb * 32);
    __syncthreads();   // T0 free for weights

    // ---- K projection ----
    stage_row(T0, Wkv + sr * 256 + shf * 64, sr, shf);
    __syncthreads();
    #pragma unroll
    for (int nt = 0; nt < 16; nt++) {
        float c[4] = {0.f, 0.f, 0.f, 0.f};
        #pragma unroll
        for (int kb = 0; kb < 8; kb++) {
            uint32_t b0, b1;
            ldsm_x2t(b0, b1, sptr(T0 + (kb * 16 + wrow) * HS + nt * 8));
            mma_f16(c, xa[kb], b0, b1);
        }
        *reinterpret_cast<uint32_t*>(T1 + (m0 + lq)     * HS + nt * 8 + 2 * lc) = packh2(c[0], c[1]);
        *reinterpret_cast<uint32_t*>(T1 + (m0 + lq + 8) * HS + nt * 8 + 2 * lc) = packh2(c[2], c[3]);
    }
    __syncthreads();

    // ---- V projection ----
    stage_row(T0, Wkv + sr * 256 + 128 + shf * 64, sr, shf);
    __syncthreads();
    #pragma unroll
    for (int nt = 0; nt < 16; nt++) {
        float c[4] = {0.f, 0.f, 0.f, 0.f};
        #pragma unroll
        for (int kb = 0; kb < 8; kb++) {
            uint32_t b0, b1;
            ldsm_x2t(b0, b1, sptr(T0 + (kb * 16 + wrow) * HS + nt * 8));
            mma_f16(c, xa[kb], b0, b1);
        }
        *reinterpret_cast<uint32_t*>(T2 + (m0 + lq)     * HS + nt * 8 + 2 * lc) = packh2(c[0], c[1]);
        *reinterpret_cast<uint32_t*>(T2 + (m0 + lq + 8) * HS + nt * 8 + 2 * lc) = packh2(c[2], c[3]);
    }
    __syncthreads();

    // ---- Q projection (registers only; scale folded) ----
    stage_row(T0, Wq + sr * 128 + shf * 64, sr, shf);
    __syncthreads();
    uint32_t qreg[16][2];
    #pragma unroll
    for (int nt = 0; nt < 16; nt++) {
        float c[4] = {0.f, 0.f, 0.f, 0.f};
        #pragma unroll
        for (int kb = 0; kb < 8; kb++) {
            uint32_t b0, b1;
            ldsm_x2t(b0, b1, sptr(T0 + (kb * 16 + wrow) * HS + nt * 8));
            mma_f16(c, xa[kb], b0, b1);
        }
        qreg[nt][0] = packh2(c[0] * 0.25f, c[1] * 0.25f);   // 1/sqrt(16)
        qreg[nt][1] = packh2(c[2] * 0.25f, c[3] * 0.25f);
    }
    __syncthreads();

    // ---- Stage Wo into T0 (read-only through phases 3-4) ----
    stage_row(T0, Wo + sr * 128 + shf * 64, sr, shf);
    __syncthreads();
    // NO MORE CTA BARRIERS from here to the end.

    // ---- Phase 3: attention; Oa accumulated in registers (A-frags for phase 4) ----
    uint32_t oa[8][4];
    for (int h = 0; h < 8; h++) {
        uint32_t sp[16][2];               // S then P, packed fp16
        float mx0 = -1e30f, mx1 = -1e30f;
        #pragma unroll
        for (int nt = 0; nt < 16; nt++) {
            float c[4] = {0.f, 0.f, 0.f, 0.f};
            uint32_t b0, b1;
            ldsm_x2(b0, b1, sptr(T1 + (nt * 8 + lr) * HS + h * 16 + ((lg & 1) << 3)));
            mma_f16(c, qreg[2 * h], b0, b1);
            mx0 = fmaxf(mx0, fmaxf(c[0], c[1]));
            mx1 = fmaxf(mx1, fmaxf(c[2], c[3]));
            sp[nt][0] = packh2(c[0], c[1]);
            sp[nt][1] = packh2(c[2], c[3]);
        }
        mx0 = fmaxf(mx0, __shfl_xor_sync(0xffffffffu, mx0, 1));
        mx0 = fmaxf(mx0, __shfl_xor_sync(0xffffffffu, mx0, 2));
        mx1 = fmaxf(mx1, __shfl_xor_sync(0xffffffffu, mx1, 1));
        mx1 = fmaxf(mx1, __shfl_xor_sync(0xffffffffu, mx1, 2));

        float l0 = 0.f, l1 = 0.f;
        #pragma unroll
        for (int nt = 0; nt < 16; nt++) {
            float2 a = unpackh2(sp[nt][0]);
            float2 b = unpackh2(sp[nt][1]);
            float e0 = __expf(a.x - mx0), e1 = __expf(a.y - mx0);
            float e2 = __expf(b.x - mx1), e3 = __expf(b.y - mx1);
            l0 += e0 + e1; l1 += e2 + e3;
            sp[nt][0] = packh2(e0, e1);
            sp[nt][1] = packh2(e2, e3);
        }
        l0 += __shfl_xor_sync(0xffffffffu, l0, 1);
        l0 += __shfl_xor_sync(0xffffffffu, l0, 2);
        l1 += __shfl_xor_sync(0xffffffffu, l1, 1);
        l1 += __shfl_xor_sync(0xffffffffu, l1, 2);

        // P @ V
        float o0[4] = {0.f, 0.f, 0.f, 0.f}, o1[4] = {0.f, 0.f, 0.f, 0.f};
        #pragma unroll
        for (int kb = 0; kb < 8; kb++) {
            uint32_t b0, b1;
            ldsm_x2t(b0, b1, sptr(T2 + (kb * 16 + wrow) * HS + h * 16));
            mma_f16(o0, sp[2 * kb], b0, b1);
            ldsm_x2t(b0, b1, sptr(T2 + (kb * 16 + wrow) * HS + h * 16 + 8));
            mma_f16(o1, sp[2 * kb], b0, b1);
        }
        const float i0 = 1.0f / l0, i1 = 1.0f / l1;
        // PV C-frag == out-proj A-frag for k-block h (rows lq/lq+8, k 2lc + {0,8})
        oa[h][0] = packh2(o0[0] * i0, o0[1] * i0);
        oa[h][1] = packh2(o0[2] * i1, o0[3] * i1);
        oa[h][2] = packh2(o1[0] * i0, o1[1] * i0);
        oa[h][3] = packh2(o1[2] * i1, o1[3] * i1);
    }

    // ---- Phase 4: out-projection + bias (+pass1 accumulate); A from registers ----
    #pragma unroll
    for (int nt = 0; nt < 16; nt++) {
        float c[4] = {0.f, 0.f, 0.f, 0.f};
        #pragma unroll
        for (int kb = 0; kb < 8; kb++) {
            uint32_t b0, b1;
            ldsm_x2t(b0, b1, sptr(T0 + (kb * 16 + wrow) * HS + nt * 8));
            mma_f16(c, oa[kb], b0, b1);
        }
        const int col = nt * 8 + 2 * lc;
        const float2 bv = *reinterpret_cast<const float2*>(bo + col);
        float* p0 = out + base + (m0 + lq)     * istride + col;
        float* p1 = out + base + (m0 + lq + 8) * istride + col;
        float2 w0 = make_float2(c[0] + bv.x, c[1] + bv.y);
        float2 w1 = make_float2(c[2] + bv.x, c[3] + bv.y);
        if (PASS == 1) {
            float2 q0 = *reinterpret_cast<const float2*>(p0);
            float2 q1 = *reinterpret_cast<const float2*>(p1);
            w0.x += q0.x; w0.y += q0.y;
            w1.x += q1.x; w1.y += q1.y;
        }
        *reinterpret_cast<float2*>(p0) = w0;
        *reinterpret_cast<float2*>(p1) = w1;
    }
}

extern "C" void kernel_launch(void* const* d_in, const int* in_sizes, int n_in,
                              void* d_out, int out_size)
{
    const float* x    = (const float*)d_in[0];
    const float* Wq0  = (const float*)d_in[1];
    const float* Wkv0 = (const float*)d_in[2];
    const float* Wo0  = (const float*)d_in[3];
    const float* bo0  = (const float*)d_in[4];
    const float* Wq1  = (const float*)d_in[5];
    const float* Wkv1 = (const float*)d_in[6];
    const float* Wo1  = (const float*)d_in[7];
    const float* bo1  = (const float*)d_in[8];
    float* out = (float*)d_out;

    cudaFuncSetAttribute(axial_attn_kernel<0>,
                         cudaFuncAttributeMaxDynamicSharedMemorySize, SMEM_BYTES);
    cudaFuncSetAttribute(axial_attn_kernel<1>,
                         cudaFuncAttributeMaxDynamicSharedMemorySize, SMEM_BYTES);

    axial_attn_kernel<0><<<1024, NTHREADS, SMEM_BYTES>>>(x, Wq0, Wkv0, Wo0, bo0, out);
    axial_attn_kernel<1><<<1024, NTHREADS, SMEM_BYTES>>>(x, Wq1, Wkv1, Wo1, bo1, out);
}